// round 16
// baseline (speedup 1.0000x reference)
#include <cuda_runtime.h>
#include <cuda_bf16.h>
#include <math.h>
#include <stdint.h>
#include <stddef.h>

#define DHID 768
#define NB   64
#define NLP  1024
#define NLQ  128

// ---------------- scratch (__device__ globals; allocation-free rule) --------
__device__ float g_qbias[NB * NLQ];
__device__ __align__(16) __nv_bfloat16 g_Wth[DHID * DHID];   // W^T hi [n][k]
__device__ __align__(16) __nv_bfloat16 g_Wtl[DHID * DHID];   // W^T lo [n][k]
__device__ __align__(16) __nv_bfloat16 g_Wph[(size_t)NB * NLP * DHID];
__device__ __align__(16) __nv_bfloat16 g_Wpl[(size_t)NB * NLP * DHID];
__device__ __align__(16) __nv_bfloat16 g_Wqh[(size_t)NB * NLQ * DHID];
__device__ __align__(16) __nv_bfloat16 g_Wql[(size_t)NB * NLQ * DHID];

// ---------------- small asm helpers ----------------------------------------
__device__ __forceinline__ uint32_t smem_u32(const void* p) {
    uint32_t a;
    asm("{ .reg .u64 t; cvta.to.shared.u64 t, %1; cvt.u32.u64 %0, t; }" : "=r"(a) : "l"(p));
    return a;
}
__device__ __forceinline__ void cp16(uint32_t dst, const void* src) {
    asm volatile("cp.async.cg.shared.global [%0], [%1], 16;" :: "r"(dst), "l"(src));
}
#define CP_COMMIT() asm volatile("cp.async.commit_group;" ::: "memory")
#define CP_WAIT0()  asm volatile("cp.async.wait_group 0;" ::: "memory")

__device__ __forceinline__ void ldsm4(uint32_t& r0, uint32_t& r1, uint32_t& r2,
                                      uint32_t& r3, uint32_t a) {
    asm volatile("ldmatrix.sync.aligned.m8n8.x4.shared.b16 {%0,%1,%2,%3}, [%4];"
                 : "=r"(r0), "=r"(r1), "=r"(r2), "=r"(r3) : "r"(a));
}
__device__ __forceinline__ void ldsm4t(uint32_t& r0, uint32_t& r1, uint32_t& r2,
                                       uint32_t& r3, uint32_t a) {
    asm volatile("ldmatrix.sync.aligned.m8n8.x4.trans.shared.b16 {%0,%1,%2,%3}, [%4];"
                 : "=r"(r0), "=r"(r1), "=r"(r2), "=r"(r3) : "r"(a));
}
__device__ __forceinline__ void mma16816(float* c, uint32_t a0, uint32_t a1,
                                         uint32_t a2, uint32_t a3,
                                         uint32_t b0, uint32_t b1) {
    asm volatile("mma.sync.aligned.m16n8k16.row.col.f32.bf16.bf16.f32 "
                 "{%0,%1,%2,%3}, {%4,%5,%6,%7}, {%8,%9}, {%0,%1,%2,%3};"
                 : "+f"(c[0]), "+f"(c[1]), "+f"(c[2]), "+f"(c[3])
                 : "r"(a0), "r"(a1), "r"(a2), "r"(a3), "r"(b0), "r"(b1));
}
__device__ __forceinline__ void split2(float v, __nv_bfloat16& h, __nv_bfloat16& l) {
    h = __float2bfloat16(v);
    l = __float2bfloat16(v - __bfloat162float(h));
}

// ---------------- mask prep (dtype-sniffing) --------------------------------
__global__ void mask_prep_kernel(const unsigned char* __restrict__ qm, int n) {
    __shared__ int mode;
    if (threadIdx.x == 0) mode = 0;
    __syncthreads();
    for (int i = threadIdx.x; i < n; i += blockDim.x) {
        int r = i & 3;
        unsigned char c = qm[i];
        if (r != 0 && c != 0) {
            if (r == 3 && c == 0x3F) atomicMax(&mode, 2);
            else                     atomicMax(&mode, 1);
        }
    }
    __syncthreads();
    int m = mode;
    for (int i = threadIdx.x; i < n; i += blockDim.x) {
        int v;
        if (m == 2)      v = (((const float*)(const void*)qm)[i] != 0.0f);
        else if (m == 1) v = (qm[i] != 0);
        else             v = (((const int*)(const void*)qm)[i] != 0);
        g_qbias[i] = v ? -1e30f : 0.0f;
    }
}

// ---------------- W[k][n] -> W^T split (hi/lo) ------------------------------
__global__ void wsplit_kernel(const float* __restrict__ W,
                              __nv_bfloat16* __restrict__ Wth,
                              __nv_bfloat16* __restrict__ Wtl) {
    __shared__ float t[32][33];
    int bx = blockIdx.x * 32;  // k
    int by = blockIdx.y * 32;  // n
    for (int yy = threadIdx.y; yy < 32; yy += 8)
        t[yy][threadIdx.x] = W[(size_t)(bx + yy) * DHID + by + threadIdx.x];
    __syncthreads();
    for (int yy = threadIdx.y; yy < 32; yy += 8) {
        float v = t[threadIdx.x][yy];
        __nv_bfloat16 h, l;
        split2(v, h, l);
        size_t o = (size_t)(by + yy) * DHID + bx + threadIdx.x;
        Wth[o] = h;
        Wtl[o] = l;
    }
}

// ---------------- common tiling constants -----------------------------------
#define GP_B      80
#define ARR_B     (128 * GP_B)
#define O_AH      0
#define O_AL      (1 * ARR_B)
#define O_BH      (2 * ARR_B)
#define O_BL      (3 * ARR_B)
#define STAGE_B   (4 * ARR_B)         // 40960
#define NCHUNK    (DHID / 32)         // 24

// B hi/lo loader (cp.async) into the standard stage layout
__device__ __forceinline__ void load_stageB(uint32_t dst, int kc, int tid,
                                            const __nv_bfloat16* __restrict__ B_h,
                                            const __nv_bfloat16* __restrict__ B_l) {
#pragma unroll
    for (int i = 0; i < 2; ++i) {
        int idx = tid + i * 256;
        int row = idx >> 2;
        int c   = idx & 3;
        uint32_t d = dst + (uint32_t)(row * GP_B + c * 16);
        size_t so = (size_t)row * DHID + kc + c * 8;
        cp16(d + O_BH, B_h + so);
        cp16(d + O_BL, B_l + so);
    }
}

// full hi/lo loader (A+B) — used by the attention kernel phase 1
__device__ __forceinline__ void load_stage(uint32_t dst, int kc, int tid,
                                           const __nv_bfloat16* __restrict__ A_h,
                                           const __nv_bfloat16* __restrict__ A_l,
                                           const __nv_bfloat16* __restrict__ B_h,
                                           const __nv_bfloat16* __restrict__ B_l) {
#pragma unroll
    for (int i = 0; i < 2; ++i) {
        int idx = tid + i * 256;
        int row = idx >> 2;
        int c   = idx & 3;
        uint32_t d = dst + (uint32_t)(row * GP_B + c * 16);
        size_t so = (size_t)row * DHID + kc + c * 8;
        cp16(d + O_AH, A_h + so);
        cp16(d + O_AL, A_l + so);
        cp16(d + O_BH, B_h + so);
        cp16(d + O_BL, B_l + so);
    }
}

// 3-product split-bf16 chunk (hi*hi, lo*hi, hi*lo per accumulator)
__device__ __forceinline__ void mma_chunk(uint32_t st, const uint32_t* aoff,
                                          const uint32_t* boff, float acc[4][4][4]) {
#pragma unroll
    for (int ks = 0; ks < 2; ++ks) {
        uint32_t k2 = (uint32_t)ks * 32;
        uint32_t ah[4][4], bh[4][2];
#pragma unroll
        for (int mi = 0; mi < 4; ++mi)
            ldsm4(ah[mi][0], ah[mi][1], ah[mi][2], ah[mi][3], st + O_AH + aoff[mi] + k2);
#pragma unroll
        for (int p = 0; p < 2; ++p) {
            uint32_t r0, r1, r2, r3;
            ldsm4(r0, r1, r2, r3, st + O_BH + boff[p] + k2);
            bh[p * 2][0] = r0; bh[p * 2][1] = r1;
            bh[p * 2 + 1][0] = r2; bh[p * 2 + 1][1] = r3;
        }
#pragma unroll
        for (int mi = 0; mi < 4; ++mi)
#pragma unroll
            for (int ni = 0; ni < 4; ++ni)
                mma16816(acc[mi][ni], ah[mi][0], ah[mi][1], ah[mi][2], ah[mi][3],
                         bh[ni][0], bh[ni][1]);

        uint32_t al[4][4];
#pragma unroll
        for (int mi = 0; mi < 4; ++mi)
            ldsm4(al[mi][0], al[mi][1], al[mi][2], al[mi][3], st + O_AL + aoff[mi] + k2);
#pragma unroll
        for (int mi = 0; mi < 4; ++mi)
#pragma unroll
            for (int ni = 0; ni < 4; ++ni)
                mma16816(acc[mi][ni], al[mi][0], al[mi][1], al[mi][2], al[mi][3],
                         bh[ni][0], bh[ni][1]);

        uint32_t bl[4][2];
#pragma unroll
        for (int p = 0; p < 2; ++p) {
            uint32_t r0, r1, r2, r3;
            ldsm4(r0, r1, r2, r3, st + O_BL + boff[p] + k2);
            bl[p * 2][0] = r0; bl[p * 2][1] = r1;
            bl[p * 2 + 1][0] = r2; bl[p * 2 + 1][1] = r3;
        }
#pragma unroll
        for (int mi = 0; mi < 4; ++mi)
#pragma unroll
            for (int ni = 0; ni < 4; ++ni)
                mma16816(acc[mi][ni], ah[mi][0], ah[mi][1], ah[mi][2], ah[mi][3],
                         bl[ni][0], bl[ni][1]);
    }
}

// ---------------- projection GEMM: direct-LDG A split, 2-stage, 2 CTAs/SM ---
// Loop order: loadB(t+1) [async] -> mma(t) -> convertA(t+1) -> wait -> sync.
#define BIAS_OFF  (2 * STAGE_B)       // 81920
#define GSMEM     (BIAS_OFF + 512)    // 82432
#define YP        ((NB * NLP) / 128)  // 512 P row-blocks

__device__ __forceinline__ void convertA_g(const float* __restrict__ Af, int kc,
                                           char* stage, int tid) {
#pragma unroll
    for (int i = 0; i < 2; ++i) {
        int idx = tid + i * 256;          // 0..511 output 16B-hi units
        int row = idx >> 2;
        int c   = idx & 3;                // 32B fp32 -> 16B hi + 16B lo
        const float4* s = (const float4*)(Af + (size_t)row * DHID + kc + c * 8);
        float4 v0 = s[0], v1 = s[1];
        float f[8] = {v0.x, v0.y, v0.z, v0.w, v1.x, v1.y, v1.z, v1.w};
        uint32_t H[4], L[4];
#pragma unroll
        for (int q = 0; q < 4; ++q) {
            __nv_bfloat16 h0, l0, h1, l1;
            split2(f[2 * q],     h0, l0);
            split2(f[2 * q + 1], h1, l1);
            __nv_bfloat162 ph(h0, h1), pl(l0, l1);
            H[q] = *reinterpret_cast<uint32_t*>(&ph);
            L[q] = *reinterpret_cast<uint32_t*>(&pl);
        }
        char* d = stage + row * GP_B + c * 16;
        *(uint4*)(d + O_AH) = make_uint4(H[0], H[1], H[2], H[3]);
        *(uint4*)(d + O_AL) = make_uint4(L[0], L[1], L[2], L[3]);
    }
}

__global__ __launch_bounds__(256, 2)
void gemm_mma_kernel(const float* __restrict__ Pf,
                     const float* __restrict__ Qf,
                     const __nv_bfloat16* __restrict__ Bh,
                     const __nv_bfloat16* __restrict__ Bl,
                     const float* __restrict__ bias,
                     __nv_bfloat16* __restrict__ Ph_out,
                     __nv_bfloat16* __restrict__ Pl_out,
                     __nv_bfloat16* __restrict__ Qh_out,
                     __nv_bfloat16* __restrict__ Ql_out) {
    extern __shared__ char smem[];
    uint32_t sb = smem_u32(smem);
    float* bias_s = (float*)(smem + BIAS_OFF);

    const int tid  = threadIdx.x;
    const int w    = tid >> 5;
    const int lane = tid & 31;
    const int wm   = w >> 2;
    const int wn   = w & 3;
    const int yb   = blockIdx.y;
    const bool isQ = (yb >= YP);
    const size_t mBase = (size_t)(isQ ? yb - YP : yb) * 128;
    const int    nBase = blockIdx.x * 128;

    if (tid < 128) bias_s[tid] = bias[nBase + tid];

    const float* Af = (isQ ? Qf : Pf) + mBase * DHID;
    const __nv_bfloat16* B_h = Bh + (size_t)nBase * DHID;
    const __nv_bfloat16* B_l = Bl + (size_t)nBase * DHID;
    __nv_bfloat16* Ch = isQ ? Qh_out : Ph_out;
    __nv_bfloat16* Cl = isQ ? Ql_out : Pl_out;

    const int j  = lane >> 3;
    const int rj = lane & 7;
    uint32_t aoff[4], boff[2];
#pragma unroll
    for (int mi = 0; mi < 4; ++mi)
        aoff[mi] = (uint32_t)((wm * 64 + mi * 16 + (j & 1) * 8 + rj) * GP_B + (j >> 1) * 16);
#pragma unroll
    for (int p = 0; p < 2; ++p)
        boff[p] = (uint32_t)((wn * 32 + p * 16 + (j >> 1) * 8 + rj) * GP_B + (j & 1) * 16);

    float acc[4][4][4];
#pragma unroll
    for (int mi = 0; mi < 4; ++mi)
#pragma unroll
        for (int ni = 0; ni < 4; ++ni)
#pragma unroll
            for (int r = 0; r < 4; ++r) acc[mi][ni][r] = 0.0f;

    // prologue: B(0) async + A(0) direct-convert into stage0
    load_stageB(sb + 0 * STAGE_B, 0, tid, B_h, B_l);
    CP_COMMIT();
    convertA_g(Af, 0, smem + 0 * STAGE_B, tid);
    CP_WAIT0();
    __syncthreads();

    for (int t = 0; t < NCHUNK; ++t) {
        if (t + 1 < NCHUNK) {
            load_stageB(sb + (uint32_t)((t + 1) & 1) * STAGE_B, (t + 1) * 32, tid,
                        B_h, B_l);
            CP_COMMIT();
        }
        mma_chunk(sb + (uint32_t)(t & 1) * STAGE_B, aoff, boff, acc);
        if (t + 1 < NCHUNK)
            convertA_g(Af, (t + 1) * 32,
                       smem + (size_t)((t + 1) & 1) * STAGE_B, tid);
        CP_WAIT0();
        __syncthreads();
    }

    // epilogue: bias + relu, split hi/lo bf16 store
    const int rGrp = lane >> 2;
    const int cGrp = (lane & 3) * 2;
#pragma unroll
    for (int mi = 0; mi < 4; ++mi) {
        size_t gr = mBase + wm * 64 + mi * 16 + rGrp;
#pragma unroll
        for (int ni = 0; ni < 4; ++ni) {
            int lc = wn * 32 + ni * 8 + cGrp;
            float b0 = bias_s[lc], b1 = bias_s[lc + 1];
            float v0 = fmaxf(acc[mi][ni][0] + b0, 0.0f);
            float v1 = fmaxf(acc[mi][ni][1] + b1, 0.0f);
            float v2 = fmaxf(acc[mi][ni][2] + b0, 0.0f);
            float v3 = fmaxf(acc[mi][ni][3] + b1, 0.0f);
            __nv_bfloat16 h0, h1, h2, h3, l0, l1, l2, l3;
            split2(v0, h0, l0); split2(v1, h1, l1);
            split2(v2, h2, l2); split2(v3, h3, l3);
            size_t o0 = gr * DHID + nBase + lc;
            size_t o1 = (gr + 8) * DHID + nBase + lc;
            *(__nv_bfloat162*)(Ch + o0) = __nv_bfloat162(h0, h1);
            *(__nv_bfloat162*)(Cl + o0) = __nv_bfloat162(l0, l1);
            *(__nv_bfloat162*)(Ch + o1) = __nv_bfloat162(h2, h3);
            *(__nv_bfloat162*)(Cl + o1) = __nv_bfloat162(l2, l3);
        }
    }
}

// ---------------- tensor-core fused attention: 2 CTAs/SM ---------------------
// phase 1 double-buffered: stage0 at 0, stage1 aliases the alpha region.
// phase 3 converts question fp32 -> hi/lo directly into stage0 (no split pass).
#define AH_OFF   40960
#define AL_OFF   75776
#define AP_B     272
#define QB_OFF   110592
#define RED_OFF  111104
#define ASMEM    113152
#define QP_B     144

// question fp32 [q=128 rows][dc*64 + 64 cols] -> hi @stage, lo @stage+18432
__device__ __forceinline__ void convertQ_g(const float* __restrict__ Qf, int dcoff,
                                           char* stage, int tid) {
#pragma unroll
    for (int i = 0; i < 4; ++i) {
        int idx = tid + i * 256;          // 0..1023 16B-hi units
        int row = idx >> 3;               // 0..127 (q row)
        int c   = idx & 7;                // 8 units per row
        const float4* s = (const float4*)(Qf + (size_t)row * DHID + dcoff + c * 8);
        float4 v0 = s[0], v1 = s[1];
        float f[8] = {v0.x, v0.y, v0.z, v0.w, v1.x, v1.y, v1.z, v1.w};
        uint32_t H[4], L[4];
#pragma unroll
        for (int q = 0; q < 4; ++q) {
            __nv_bfloat16 h0, l0, h1, l1;
            split2(f[2 * q],     h0, l0);
            split2(f[2 * q + 1], h1, l1);
            __nv_bfloat162 ph(h0, h1), pl(l0, l1);
            H[q] = *reinterpret_cast<uint32_t*>(&ph);
            L[q] = *reinterpret_cast<uint32_t*>(&pl);
        }
        char* d = stage + row * QP_B + c * 16;
        *(uint4*)d             = make_uint4(H[0], H[1], H[2], H[3]);
        *(uint4*)(d + 18432)   = make_uint4(L[0], L[1], L[2], L[3]);
    }
}

__global__ __launch_bounds__(256, 2)
void attn_tc_kernel(const __nv_bfloat16* __restrict__ Wph,
                    const __nv_bfloat16* __restrict__ Wpl,
                    const __nv_bfloat16* __restrict__ Wqh,
                    const __nv_bfloat16* __restrict__ Wql,
                    const float* __restrict__ question,
                    float* __restrict__ out) {
    extern __shared__ char smem[];
    uint32_t sb = smem_u32(smem);
    float* qb  = (float*)(smem + QB_OFF);
    float* red = (float*)(smem + RED_OFF);

    const int tid  = threadIdx.x;
    const int w    = tid >> 5;
    const int lane = tid & 31;
    const int wm   = w >> 2;
    const int wn   = w & 3;
    const int b    = blockIdx.y;
    const int pBase = blockIdx.x * 128;

    if (tid < 128) qb[tid] = g_qbias[b * NLQ + tid];

    const __nv_bfloat16* A_h = Wph + ((size_t)b * NLP + pBase) * DHID;
    const __nv_bfloat16* A_l = Wpl + ((size_t)b * NLP + pBase) * DHID;
    const __nv_bfloat16* B_h = Wqh + (size_t)b * NLQ * DHID;
    const __nv_bfloat16* B_l = Wql + (size_t)b * NLQ * DHID;
    const float* Qf = question + (size_t)b * NLQ * DHID;

    const int j  = lane >> 3;
    const int rj = lane & 7;
    const int rGrp = lane >> 2;
    const int cGrp = (lane & 3) * 2;

    // ---- phase 1: scores = Wp @ Wq^T, 2-stage (stage1 aliases alpha region) ----
    float acc[4][4][4];
#pragma unroll
    for (int mi = 0; mi < 4; ++mi)
#pragma unroll
        for (int ni = 0; ni < 4; ++ni)
#pragma unroll
            for (int r = 0; r < 4; ++r) acc[mi][ni][r] = 0.0f;
    {
        uint32_t aoff[4], boff[2];
#pragma unroll
        for (int mi = 0; mi < 4; ++mi)
            aoff[mi] = (uint32_t)((wm * 64 + mi * 16 + (j & 1) * 8 + rj) * GP_B + (j >> 1) * 16);
#pragma unroll
        for (int p = 0; p < 2; ++p)
            boff[p] = (uint32_t)((wn * 32 + p * 16 + (j >> 1) * 8 + rj) * GP_B + (j & 1) * 16);

        load_stage(sb, 0, tid, A_h, A_l, B_h, B_l);
        CP_COMMIT();
        for (int t = 0; t < NCHUNK; ++t) {
            CP_WAIT0();
            __syncthreads();
            if (t + 1 < NCHUNK) {
                load_stage(sb + (uint32_t)(((t + 1) & 1) ? AH_OFF : 0),
                           (t + 1) * 32, tid, A_h, A_l, B_h, B_l);
                CP_COMMIT();
            }
            mma_chunk(sb + (uint32_t)((t & 1) ? AH_OFF : 0), aoff, boff, acc);
        }
    }

    // convert Q(dc=0) into stage0 (dead after chunk 22; this warp's mma done,
    // other warps' pending mma read only the AH region)
    convertQ_g(Qf, 0, smem, tid);

    // ---- phase 2: mask bias + softmax in registers ----
    {
#pragma unroll
        for (int mi = 0; mi < 4; ++mi)
#pragma unroll
            for (int ni = 0; ni < 4; ++ni) {
                int q0 = wn * 32 + ni * 8 + cGrp;
                float b0 = qb[q0], b1 = qb[q0 + 1];
                acc[mi][ni][0] += b0; acc[mi][ni][1] += b1;
                acc[mi][ni][2] += b0; acc[mi][ni][3] += b1;
            }

        float mrow[4][2];
#pragma unroll
        for (int mi = 0; mi < 4; ++mi) {
            mrow[mi][0] = -INFINITY; mrow[mi][1] = -INFINITY;
#pragma unroll
            for (int ni = 0; ni < 4; ++ni) {
                mrow[mi][0] = fmaxf(mrow[mi][0], fmaxf(acc[mi][ni][0], acc[mi][ni][1]));
                mrow[mi][1] = fmaxf(mrow[mi][1], fmaxf(acc[mi][ni][2], acc[mi][ni][3]));
            }
        }
#pragma unroll
        for (int o = 1; o <= 2; o <<= 1)
#pragma unroll
            for (int mi = 0; mi < 4; ++mi) {
                mrow[mi][0] = fmaxf(mrow[mi][0], __shfl_xor_sync(0xFFFFFFFFu, mrow[mi][0], o));
                mrow[mi][1] = fmaxf(mrow[mi][1], __shfl_xor_sync(0xFFFFFFFFu, mrow[mi][1], o));
            }
        if ((lane & 3) == 0)
#pragma unroll
            for (int mi = 0; mi < 4; ++mi) {
                red[(wm * 64 + mi * 16 + rGrp) * 4 + wn]     = mrow[mi][0];
                red[(wm * 64 + mi * 16 + rGrp + 8) * 4 + wn] = mrow[mi][1];
            }
        __syncthreads();
        float M[4][2];
#pragma unroll
        for (int mi = 0; mi < 4; ++mi)
#pragma unroll
            for (int h = 0; h < 2; ++h) {
                const float* rr = &red[(wm * 64 + mi * 16 + rGrp + h * 8) * 4];
                M[mi][h] = fmaxf(fmaxf(rr[0], rr[1]), fmaxf(rr[2], rr[3]));
            }
        __syncthreads();

        float srow[4][2];
#pragma unroll
        for (int mi = 0; mi < 4; ++mi) { srow[mi][0] = 0.0f; srow[mi][1] = 0.0f; }
#pragma unroll
        for (int mi = 0; mi < 4; ++mi)
#pragma unroll
            for (int ni = 0; ni < 4; ++ni) {
                float e0 = __expf(acc[mi][ni][0] - M[mi][0]);
                float e1 = __expf(acc[mi][ni][1] - M[mi][0]);
                float e2 = __expf(acc[mi][ni][2] - M[mi][1]);
                float e3 = __expf(acc[mi][ni][3] - M[mi][1]);
                acc[mi][ni][0] = e0; acc[mi][ni][1] = e1;
                acc[mi][ni][2] = e2; acc[mi][ni][3] = e3;
                srow[mi][0] += e0 + e1;
                srow[mi][1] += e2 + e3;
            }
#pragma unroll
        for (int o = 1; o <= 2; o <<= 1)
#pragma unroll
            for (int mi = 0; mi < 4; ++mi) {
                srow[mi][0] += __shfl_xor_sync(0xFFFFFFFFu, srow[mi][0], o);
                srow[mi][1] += __shfl_xor_sync(0xFFFFFFFFu, srow[mi][1], o);
            }
        if ((lane & 3) == 0)
#pragma unroll
            for (int mi = 0; mi < 4; ++mi) {
                red[(wm * 64 + mi * 16 + rGrp) * 4 + wn]     = srow[mi][0];
                red[(wm * 64 + mi * 16 + rGrp + 8) * 4 + wn] = srow[mi][1];
            }
        __syncthreads();
        float INV[4][2];
#pragma unroll
        for (int mi = 0; mi < 4; ++mi)
#pragma unroll
            for (int h = 0; h < 2; ++h) {
                const float* rr = &red[(wm * 64 + mi * 16 + rGrp + h * 8) * 4];
                INV[mi][h] = 1.0f / (rr[0] + rr[1] + rr[2] + rr[3]);
            }

#pragma unroll
        for (int mi = 0; mi < 4; ++mi) {
            int pr = wm * 64 + mi * 16 + rGrp;
#pragma unroll
            for (int ni = 0; ni < 4; ++ni) {
                int q0 = wn * 32 + ni * 8 + cGrp;
                float a0 = acc[mi][ni][0] * INV[mi][0];
                float a1 = acc[mi][ni][1] * INV[mi][0];
                float a2 = acc[mi][ni][2] * INV[mi][1];
                float a3 = acc[mi][ni][3] * INV[mi][1];
                __nv_bfloat16 h0, h1, h2, h3, l0, l1, l2, l3;
                split2(a0, h0, l0); split2(a1, h1, l1);
                split2(a2, h2, l2); split2(a3, h3, l3);
                *(__nv_bfloat162*)(smem + AH_OFF + pr * AP_B + q0 * 2)       = __nv_bfloat162(h0, h1);
                *(__nv_bfloat162*)(smem + AL_OFF + pr * AP_B + q0 * 2)       = __nv_bfloat162(l0, l1);
                *(__nv_bfloat162*)(smem + AH_OFF + (pr + 8) * AP_B + q0 * 2) = __nv_bfloat162(h2, h3);
                *(__nv_bfloat162*)(smem + AL_OFF + (pr + 8) * AP_B + q0 * 2) = __nv_bfloat162(l2, l3);
            }
        }
    }
    __syncthreads();

    // ---- phase 3: out = alpha @ question; Q converted fp32->hi/lo per dc ----
    {
        uint32_t aoff3[4];
#pragma unroll
        for (int mi = 0; mi < 4; ++mi)
            aoff3[mi] = (uint32_t)(AH_OFF + (wm * 64 + mi * 16 + (j & 1) * 8 + rj) * AP_B + (j >> 1) * 16);
        uint32_t boffq = (uint32_t)(((j & 1) * 8 + rj) * QP_B + wn * 32 + (j >> 1) * 16);
        const uint32_t dAL = AL_OFF - AH_OFF;

        for (int dc = 0; dc < 12; ++dc) {
            if (dc > 0) {
                __syncthreads();   // WAR: all ldsm of Q(dc-1) complete
                convertQ_g(Qf, dc * 64, smem, tid);
                __syncthreads();   // STS visible
            }

            float o3[4][2][4];
#pragma unroll
            for (int mi = 0; mi < 4; ++mi)
#pragma unroll
                for (int ni = 0; ni < 2; ++ni)
#pragma unroll
                    for (int r = 0; r < 4; ++r) o3[mi][ni][r] = 0.0f;

#pragma unroll
            for (int ks = 0; ks < 8; ++ks) {
                uint32_t ka = (uint32_t)ks * 32;
                uint32_t kq = (uint32_t)ks * 16 * QP_B;
                uint32_t ah[4][4], bh[2][2];
#pragma unroll
                for (int mi = 0; mi < 4; ++mi)
                    ldsm4(ah[mi][0], ah[mi][1], ah[mi][2], ah[mi][3],
                          sb + aoff3[mi] + ka);
                {
                    uint32_t r0, r1, r2, r3;
                    ldsm4t(r0, r1, r2, r3, sb + boffq + kq);
                    bh[0][0] = r0; bh[0][1] = r1; bh[1][0] = r2; bh[1][1] = r3;
                }
#pragma unroll
                for (int mi = 0; mi < 4; ++mi)
#pragma unroll
                    for (int ni = 0; ni < 2; ++ni)
                        mma16816(o3[mi][ni], ah[mi][0], ah[mi][1], ah[mi][2], ah[mi][3],
                                 bh[ni][0], bh[ni][1]);
                uint32_t al[4][4];
#pragma unroll
                for (int mi = 0; mi < 4; ++mi)
                    ldsm4(al[mi][0], al[mi][1], al[mi][2], al[mi][3],
                          sb + aoff3[mi] + dAL + ka);
#pragma unroll
                for (int mi = 0; mi < 4; ++mi)
#pragma unroll
                    for (int ni = 0; ni < 2; ++ni)
                        mma16816(o3[mi][ni], al[mi][0], al[mi][1], al[mi][2], al[mi][3],
                                 bh[ni][0], bh[ni][1]);
                uint32_t bl[2][2];
                {
                    uint32_t r0, r1, r2, r3;
                    ldsm4t(r0, r1, r2, r3, sb + 18432 + boffq + kq);
                    bl[0][0] = r0; bl[0][1] = r1; bl[1][0] = r2; bl[1][1] = r3;
                }
#pragma unroll
                for (int mi = 0; mi < 4; ++mi)
#pragma unroll
                    for (int ni = 0; ni < 2; ++ni)
                        mma16816(o3[mi][ni], ah[mi][0], ah[mi][1], ah[mi][2], ah[mi][3],
                                 bl[ni][0], bl[ni][1]);
            }

#pragma unroll
            for (int mi = 0; mi < 4; ++mi) {
                size_t gr = (size_t)b * NLP + pBase + wm * 64 + mi * 16 + rGrp;
#pragma unroll
                for (int ni = 0; ni < 2; ++ni) {
                    int d = dc * 64 + wn * 16 + ni * 8 + cGrp;
                    float2 v0 = {o3[mi][ni][0], o3[mi][ni][1]};
                    float2 v1 = {o3[mi][ni][2], o3[mi][ni][3]};
                    *(float2*)(out + gr * DHID + d)       = v0;
                    *(float2*)(out + (gr + 8) * DHID + d) = v1;
                }
            }
        }
    }
}

// ---------------------------------------------------------------------------
extern "C" void kernel_launch(void* const* d_in, const int* in_sizes, int n_in,
                              void* d_out, int out_size) {
    const float* passage  = (const float*)d_in[0];
    const float* question = (const float*)d_in[2];
    const unsigned char* qmask = (const unsigned char*)d_in[3];
    const float* Ww = (const float*)d_in[4];
    const float* Wb = (const float*)d_in[5];
    float* out = (float*)d_out;

    __nv_bfloat16 *wth, *wtl, *wph, *wpl, *wqh, *wql;
    cudaGetSymbolAddress((void**)&wth, g_Wth);
    cudaGetSymbolAddress((void**)&wtl, g_Wtl);
    cudaGetSymbolAddress((void**)&wph, g_Wph);
    cudaGetSymbolAddress((void**)&wpl, g_Wpl);
    cudaGetSymbolAddress((void**)&wqh, g_Wqh);
    cudaGetSymbolAddress((void**)&wql, g_Wql);

    mask_prep_kernel<<<1, 256>>>(qmask, NB * NLQ);
    wsplit_kernel<<<dim3(DHID / 32, DHID / 32), dim3(32, 8)>>>(Ww, wth, wtl);

    cudaFuncSetAttribute(gemm_mma_kernel, cudaFuncAttributeMaxDynamicSharedMemorySize, GSMEM);
    gemm_mma_kernel<<<dim3(DHID / 128, YP + (NB * NLQ) / 128), 256, GSMEM>>>(
        passage, question, wth, wtl, Wb, wph, wpl, wqh, wql);

    cudaFuncSetAttribute(attn_tc_kernel, cudaFuncAttributeMaxDynamicSharedMemorySize, ASMEM);
    attn_tc_kernel<<<dim3(NLP / 128, NB), 256, ASMEM>>>(wph, wpl, wqh, wql, question, out);
}

// round 17
// speedup vs baseline: 1.0165x; 1.0165x over previous
#include <cuda_runtime.h>
#include <cuda_bf16.h>
#include <math.h>
#include <stdint.h>
#include <stddef.h>

#define DHID 768
#define NB   64
#define NLP  1024
#define NLQ  128

// ---------------- scratch (__device__ globals; allocation-free rule) --------
__device__ float g_qbias[NB * NLQ];
__device__ __align__(16) __nv_bfloat16 g_Wth[DHID * DHID];   // W^T hi [n][k]
__device__ __align__(16) __nv_bfloat16 g_Wtl[DHID * DHID];   // W^T lo [n][k]
__device__ __align__(16) __nv_bfloat16 g_Wph[(size_t)NB * NLP * DHID];
__device__ __align__(16) __nv_bfloat16 g_Wpl[(size_t)NB * NLP * DHID];
__device__ __align__(16) __nv_bfloat16 g_Wqh[(size_t)NB * NLQ * DHID];
__device__ __align__(16) __nv_bfloat16 g_Wql[(size_t)NB * NLQ * DHID];

// ---------------- small asm helpers ----------------------------------------
__device__ __forceinline__ uint32_t smem_u32(const void* p) {
    uint32_t a;
    asm("{ .reg .u64 t; cvta.to.shared.u64 t, %1; cvt.u32.u64 %0, t; }" : "=r"(a) : "l"(p));
    return a;
}
__device__ __forceinline__ void cp16(uint32_t dst, const void* src) {
    asm volatile("cp.async.cg.shared.global [%0], [%1], 16;" :: "r"(dst), "l"(src));
}
#define CP_COMMIT() asm volatile("cp.async.commit_group;" ::: "memory")
#define CP_WAIT0()  asm volatile("cp.async.wait_group 0;" ::: "memory")

__device__ __forceinline__ void ldsm4(uint32_t& r0, uint32_t& r1, uint32_t& r2,
                                      uint32_t& r3, uint32_t a) {
    asm volatile("ldmatrix.sync.aligned.m8n8.x4.shared.b16 {%0,%1,%2,%3}, [%4];"
                 : "=r"(r0), "=r"(r1), "=r"(r2), "=r"(r3) : "r"(a));
}
__device__ __forceinline__ void ldsm4t(uint32_t& r0, uint32_t& r1, uint32_t& r2,
                                       uint32_t& r3, uint32_t a) {
    asm volatile("ldmatrix.sync.aligned.m8n8.x4.trans.shared.b16 {%0,%1,%2,%3}, [%4];"
                 : "=r"(r0), "=r"(r1), "=r"(r2), "=r"(r3) : "r"(a));
}
__device__ __forceinline__ void mma16816(float* c, uint32_t a0, uint32_t a1,
                                         uint32_t a2, uint32_t a3,
                                         uint32_t b0, uint32_t b1) {
    asm volatile("mma.sync.aligned.m16n8k16.row.col.f32.bf16.bf16.f32 "
                 "{%0,%1,%2,%3}, {%4,%5,%6,%7}, {%8,%9}, {%0,%1,%2,%3};"
                 : "+f"(c[0]), "+f"(c[1]), "+f"(c[2]), "+f"(c[3])
                 : "r"(a0), "r"(a1), "r"(a2), "r"(a3), "r"(b0), "r"(b1));
}
__device__ __forceinline__ void split2(float v, __nv_bfloat16& h, __nv_bfloat16& l) {
    h = __float2bfloat16(v);
    l = __float2bfloat16(v - __bfloat162float(h));
}

// ---------------- mask prep (dtype-sniffing) --------------------------------
__global__ void mask_prep_kernel(const unsigned char* __restrict__ qm, int n) {
    __shared__ int mode;
    if (threadIdx.x == 0) mode = 0;
    __syncthreads();
    for (int i = threadIdx.x; i < n; i += blockDim.x) {
        int r = i & 3;
        unsigned char c = qm[i];
        if (r != 0 && c != 0) {
            if (r == 3 && c == 0x3F) atomicMax(&mode, 2);
            else                     atomicMax(&mode, 1);
        }
    }
    __syncthreads();
    int m = mode;
    for (int i = threadIdx.x; i < n; i += blockDim.x) {
        int v;
        if (m == 2)      v = (((const float*)(const void*)qm)[i] != 0.0f);
        else if (m == 1) v = (qm[i] != 0);
        else             v = (((const int*)(const void*)qm)[i] != 0);
        g_qbias[i] = v ? -1e30f : 0.0f;
    }
}

// ---------------- W[k][n] -> W^T split (hi/lo) ------------------------------
__global__ void wsplit_kernel(const float* __restrict__ W,
                              __nv_bfloat16* __restrict__ Wth,
                              __nv_bfloat16* __restrict__ Wtl) {
    __shared__ float t[32][33];
    int bx = blockIdx.x * 32;  // k
    int by = blockIdx.y * 32;  // n
    for (int yy = threadIdx.y; yy < 32; yy += 8)
        t[yy][threadIdx.x] = W[(size_t)(bx + yy) * DHID + by + threadIdx.x];
    __syncthreads();
    for (int yy = threadIdx.y; yy < 32; yy += 8) {
        float v = t[threadIdx.x][yy];
        __nv_bfloat16 h, l;
        split2(v, h, l);
        size_t o = (size_t)(by + yy) * DHID + bx + threadIdx.x;
        Wth[o] = h;
        Wtl[o] = l;
    }
}

// ---------------- common tiling constants -----------------------------------
#define GP_B      80
#define ARR_B     (128 * GP_B)
#define O_AH      0
#define O_AL      (1 * ARR_B)
#define O_BH      (2 * ARR_B)
#define O_BL      (3 * ARR_B)
#define STAGE_B   (4 * ARR_B)         // 40960
#define NCHUNK    (DHID / 32)         // 24

// B hi/lo loader (cp.async) into the standard stage layout
__device__ __forceinline__ void load_stageB(uint32_t dst, int kc, int tid,
                                            const __nv_bfloat16* __restrict__ B_h,
                                            const __nv_bfloat16* __restrict__ B_l) {
#pragma unroll
    for (int i = 0; i < 2; ++i) {
        int idx = tid + i * 256;
        int row = idx >> 2;
        int c   = idx & 3;
        uint32_t d = dst + (uint32_t)(row * GP_B + c * 16);
        size_t so = (size_t)row * DHID + kc + c * 8;
        cp16(d + O_BH, B_h + so);
        cp16(d + O_BL, B_l + so);
    }
}

// full hi/lo loader (A+B) — used by the attention kernel phase 1
__device__ __forceinline__ void load_stage(uint32_t dst, int kc, int tid,
                                           const __nv_bfloat16* __restrict__ A_h,
                                           const __nv_bfloat16* __restrict__ A_l,
                                           const __nv_bfloat16* __restrict__ B_h,
                                           const __nv_bfloat16* __restrict__ B_l) {
#pragma unroll
    for (int i = 0; i < 2; ++i) {
        int idx = tid + i * 256;
        int row = idx >> 2;
        int c   = idx & 3;
        uint32_t d = dst + (uint32_t)(row * GP_B + c * 16);
        size_t so = (size_t)row * DHID + kc + c * 8;
        cp16(d + O_AH, A_h + so);
        cp16(d + O_AL, A_l + so);
        cp16(d + O_BH, B_h + so);
        cp16(d + O_BL, B_l + so);
    }
}

// 3-product split-bf16 chunk (hi*hi, lo*hi, hi*lo per accumulator)
__device__ __forceinline__ void mma_chunk(uint32_t st, const uint32_t* aoff,
                                          const uint32_t* boff, float acc[4][4][4]) {
#pragma unroll
    for (int ks = 0; ks < 2; ++ks) {
        uint32_t k2 = (uint32_t)ks * 32;
        uint32_t ah[4][4], bh[4][2];
#pragma unroll
        for (int mi = 0; mi < 4; ++mi)
            ldsm4(ah[mi][0], ah[mi][1], ah[mi][2], ah[mi][3], st + O_AH + aoff[mi] + k2);
#pragma unroll
        for (int p = 0; p < 2; ++p) {
            uint32_t r0, r1, r2, r3;
            ldsm4(r0, r1, r2, r3, st + O_BH + boff[p] + k2);
            bh[p * 2][0] = r0; bh[p * 2][1] = r1;
            bh[p * 2 + 1][0] = r2; bh[p * 2 + 1][1] = r3;
        }
#pragma unroll
        for (int mi = 0; mi < 4; ++mi)
#pragma unroll
            for (int ni = 0; ni < 4; ++ni)
                mma16816(acc[mi][ni], ah[mi][0], ah[mi][1], ah[mi][2], ah[mi][3],
                         bh[ni][0], bh[ni][1]);

        uint32_t al[4][4];
#pragma unroll
        for (int mi = 0; mi < 4; ++mi)
            ldsm4(al[mi][0], al[mi][1], al[mi][2], al[mi][3], st + O_AL + aoff[mi] + k2);
#pragma unroll
        for (int mi = 0; mi < 4; ++mi)
#pragma unroll
            for (int ni = 0; ni < 4; ++ni)
                mma16816(acc[mi][ni], al[mi][0], al[mi][1], al[mi][2], al[mi][3],
                         bh[ni][0], bh[ni][1]);

        uint32_t bl[4][2];
#pragma unroll
        for (int p = 0; p < 2; ++p) {
            uint32_t r0, r1, r2, r3;
            ldsm4(r0, r1, r2, r3, st + O_BL + boff[p] + k2);
            bl[p * 2][0] = r0; bl[p * 2][1] = r1;
            bl[p * 2 + 1][0] = r2; bl[p * 2 + 1][1] = r3;
        }
#pragma unroll
        for (int mi = 0; mi < 4; ++mi)
#pragma unroll
            for (int ni = 0; ni < 4; ++ni)
                mma16816(acc[mi][ni], ah[mi][0], ah[mi][1], ah[mi][2], ah[mi][3],
                         bl[ni][0], bl[ni][1]);
    }
}

// ---------------- projection GEMM: direct-LDG A split, 2-stage, 2 CTAs/SM ---
// R14 loop order: loadB(t+1) -> convertA(t+1) -> mma(t) -> wait -> sync.
#define BIAS_OFF  (2 * STAGE_B)       // 81920
#define GSMEM     (BIAS_OFF + 512)    // 82432
#define YP        ((NB * NLP) / 128)  // 512 P row-blocks

__device__ __forceinline__ void convertA_g(const float* __restrict__ Af, int kc,
                                           char* stage, int tid) {
#pragma unroll
    for (int i = 0; i < 2; ++i) {
        int idx = tid + i * 256;          // 0..511 output 16B-hi units
        int row = idx >> 2;
        int c   = idx & 3;                // 32B fp32 -> 16B hi + 16B lo
        const float4* s = (const float4*)(Af + (size_t)row * DHID + kc + c * 8);
        float4 v0 = s[0], v1 = s[1];
        float f[8] = {v0.x, v0.y, v0.z, v0.w, v1.x, v1.y, v1.z, v1.w};
        uint32_t H[4], L[4];
#pragma unroll
        for (int q = 0; q < 4; ++q) {
            __nv_bfloat16 h0, l0, h1, l1;
            split2(f[2 * q],     h0, l0);
            split2(f[2 * q + 1], h1, l1);
            __nv_bfloat162 ph(h0, h1), pl(l0, l1);
            H[q] = *reinterpret_cast<uint32_t*>(&ph);
            L[q] = *reinterpret_cast<uint32_t*>(&pl);
        }
        char* d = stage + row * GP_B + c * 16;
        *(uint4*)(d + O_AH) = make_uint4(H[0], H[1], H[2], H[3]);
        *(uint4*)(d + O_AL) = make_uint4(L[0], L[1], L[2], L[3]);
    }
}

__global__ __launch_bounds__(256, 2)
void gemm_mma_kernel(const float* __restrict__ Pf,
                     const float* __restrict__ Qf,
                     const __nv_bfloat16* __restrict__ Bh,
                     const __nv_bfloat16* __restrict__ Bl,
                     const float* __restrict__ bias,
                     __nv_bfloat16* __restrict__ Ph_out,
                     __nv_bfloat16* __restrict__ Pl_out,
                     __nv_bfloat16* __restrict__ Qh_out,
                     __nv_bfloat16* __restrict__ Ql_out) {
    extern __shared__ char smem[];
    uint32_t sb = smem_u32(smem);
    float* bias_s = (float*)(smem + BIAS_OFF);

    const int tid  = threadIdx.x;
    const int w    = tid >> 5;
    const int lane = tid & 31;
    const int wm   = w >> 2;
    const int wn   = w & 3;
    const int yb   = blockIdx.y;
    const bool isQ = (yb >= YP);
    const size_t mBase = (size_t)(isQ ? yb - YP : yb) * 128;
    const int    nBase = blockIdx.x * 128;

    if (tid < 128) bias_s[tid] = bias[nBase + tid];

    const float* Af = (isQ ? Qf : Pf) + mBase * DHID;
    const __nv_bfloat16* B_h = Bh + (size_t)nBase * DHID;
    const __nv_bfloat16* B_l = Bl + (size_t)nBase * DHID;
    __nv_bfloat16* Ch = isQ ? Qh_out : Ph_out;
    __nv_bfloat16* Cl = isQ ? Ql_out : Pl_out;

    const int j  = lane >> 3;
    const int rj = lane & 7;
    uint32_t aoff[4], boff[2];
#pragma unroll
    for (int mi = 0; mi < 4; ++mi)
        aoff[mi] = (uint32_t)((wm * 64 + mi * 16 + (j & 1) * 8 + rj) * GP_B + (j >> 1) * 16);
#pragma unroll
    for (int p = 0; p < 2; ++p)
        boff[p] = (uint32_t)((wn * 32 + p * 16 + (j >> 1) * 8 + rj) * GP_B + (j & 1) * 16);

    float acc[4][4][4];
#pragma unroll
    for (int mi = 0; mi < 4; ++mi)
#pragma unroll
        for (int ni = 0; ni < 4; ++ni)
#pragma unroll
            for (int r = 0; r < 4; ++r) acc[mi][ni][r] = 0.0f;

    // prologue: B(0) async + A(0) direct-convert into stage0
    load_stageB(sb + 0 * STAGE_B, 0, tid, B_h, B_l);
    CP_COMMIT();
    convertA_g(Af, 0, smem + 0 * STAGE_B, tid);
    CP_WAIT0();
    __syncthreads();

    for (int t = 0; t < NCHUNK; ++t) {
        if (t + 1 < NCHUNK) {
            load_stageB(sb + (uint32_t)((t + 1) & 1) * STAGE_B, (t + 1) * 32, tid,
                        B_h, B_l);
            CP_COMMIT();
            convertA_g(Af, (t + 1) * 32,
                       smem + (size_t)((t + 1) & 1) * STAGE_B, tid);
        }
        mma_chunk(sb + (uint32_t)(t & 1) * STAGE_B, aoff, boff, acc);
        CP_WAIT0();
        __syncthreads();
    }

    // epilogue: bias + relu, split hi/lo bf16 store
    const int rGrp = lane >> 2;
    const int cGrp = (lane & 3) * 2;
#pragma unroll
    for (int mi = 0; mi < 4; ++mi) {
        size_t gr = mBase + wm * 64 + mi * 16 + rGrp;
#pragma unroll
        for (int ni = 0; ni < 4; ++ni) {
            int lc = wn * 32 + ni * 8 + cGrp;
            float b0 = bias_s[lc], b1 = bias_s[lc + 1];
            float v0 = fmaxf(acc[mi][ni][0] + b0, 0.0f);
            float v1 = fmaxf(acc[mi][ni][1] + b1, 0.0f);
            float v2 = fmaxf(acc[mi][ni][2] + b0, 0.0f);
            float v3 = fmaxf(acc[mi][ni][3] + b1, 0.0f);
            __nv_bfloat16 h0, h1, h2, h3, l0, l1, l2, l3;
            split2(v0, h0, l0); split2(v1, h1, l1);
            split2(v2, h2, l2); split2(v3, h3, l3);
            size_t o0 = gr * DHID + nBase + lc;
            size_t o1 = (gr + 8) * DHID + nBase + lc;
            *(__nv_bfloat162*)(Ch + o0) = __nv_bfloat162(h0, h1);
            *(__nv_bfloat162*)(Cl + o0) = __nv_bfloat162(l0, l1);
            *(__nv_bfloat162*)(Ch + o1) = __nv_bfloat162(h2, h3);
            *(__nv_bfloat162*)(Cl + o1) = __nv_bfloat162(l2, l3);
        }
    }
}

// ---------------- tensor-core fused attention: 2 CTAs/SM ---------------------
// phase 1 double-buffered: stage0 at 0, stage1 aliases the alpha region.
// phase 3 converts question fp32 -> hi/lo directly into stage0 (no split pass).
#define AH_OFF   40960
#define AL_OFF   75776
#define AP_B     272
#define QB_OFF   110592
#define RED_OFF  111104
#define ASMEM    113152
#define QP_B     144

// question fp32 [q=128 rows][dcoff + 64 cols] -> hi @stage, lo @stage+18432
__device__ __forceinline__ void convertQ_g(const float* __restrict__ Qf, int dcoff,
                                           char* stage, int tid) {
#pragma unroll
    for (int i = 0; i < 4; ++i) {
        int idx = tid + i * 256;          // 0..1023 16B-hi units
        int row = idx >> 3;               // 0..127 (q row)
        int c   = idx & 7;                // 8 units per row
        const float4* s = (const float4*)(Qf + (size_t)row * DHID + dcoff + c * 8);
        float4 v0 = s[0], v1 = s[1];
        float f[8] = {v0.x, v0.y, v0.z, v0.w, v1.x, v1.y, v1.z, v1.w};
        uint32_t H[4], L[4];
#pragma unroll
        for (int q = 0; q < 4; ++q) {
            __nv_bfloat16 h0, l0, h1, l1;
            split2(f[2 * q],     h0, l0);
            split2(f[2 * q + 1], h1, l1);
            __nv_bfloat162 ph(h0, h1), pl(l0, l1);
            H[q] = *reinterpret_cast<uint32_t*>(&ph);
            L[q] = *reinterpret_cast<uint32_t*>(&pl);
        }
        char* d = stage + row * QP_B + c * 16;
        *(uint4*)d             = make_uint4(H[0], H[1], H[2], H[3]);
        *(uint4*)(d + 18432)   = make_uint4(L[0], L[1], L[2], L[3]);
    }
}

__global__ __launch_bounds__(256, 2)
void attn_tc_kernel(const __nv_bfloat16* __restrict__ Wph,
                    const __nv_bfloat16* __restrict__ Wpl,
                    const __nv_bfloat16* __restrict__ Wqh,
                    const __nv_bfloat16* __restrict__ Wql,
                    const float* __restrict__ question,
                    float* __restrict__ out) {
    extern __shared__ char smem[];
    uint32_t sb = smem_u32(smem);
    float* qb  = (float*)(smem + QB_OFF);
    float* red = (float*)(smem + RED_OFF);

    const int tid  = threadIdx.x;
    const int w    = tid >> 5;
    const int lane = tid & 31;
    const int wm   = w >> 2;
    const int wn   = w & 3;
    const int b    = blockIdx.y;
    const int pBase = blockIdx.x * 128;

    if (tid < 128) qb[tid] = g_qbias[b * NLQ + tid];

    const __nv_bfloat16* A_h = Wph + ((size_t)b * NLP + pBase) * DHID;
    const __nv_bfloat16* A_l = Wpl + ((size_t)b * NLP + pBase) * DHID;
    const __nv_bfloat16* B_h = Wqh + (size_t)b * NLQ * DHID;
    const __nv_bfloat16* B_l = Wql + (size_t)b * NLQ * DHID;
    const float* Qf = question + (size_t)b * NLQ * DHID;

    const int j  = lane >> 3;
    const int rj = lane & 7;
    const int rGrp = lane >> 2;
    const int cGrp = (lane & 3) * 2;

    // ---- phase 1: scores = Wp @ Wq^T, 2-stage (stage1 aliases alpha region) ----
    float acc[4][4][4];
#pragma unroll
    for (int mi = 0; mi < 4; ++mi)
#pragma unroll
        for (int ni = 0; ni < 4; ++ni)
#pragma unroll
            for (int r = 0; r < 4; ++r) acc[mi][ni][r] = 0.0f;
    {
        uint32_t aoff[4], boff[2];
#pragma unroll
        for (int mi = 0; mi < 4; ++mi)
            aoff[mi] = (uint32_t)((wm * 64 + mi * 16 + (j & 1) * 8 + rj) * GP_B + (j >> 1) * 16);
#pragma unroll
        for (int p = 0; p < 2; ++p)
            boff[p] = (uint32_t)((wn * 32 + p * 16 + (j >> 1) * 8 + rj) * GP_B + (j & 1) * 16);

        load_stage(sb, 0, tid, A_h, A_l, B_h, B_l);
        CP_COMMIT();
        for (int t = 0; t < NCHUNK; ++t) {
            CP_WAIT0();
            __syncthreads();
            if (t + 1 < NCHUNK) {
                load_stage(sb + (uint32_t)(((t + 1) & 1) ? AH_OFF : 0),
                           (t + 1) * 32, tid, A_h, A_l, B_h, B_l);
                CP_COMMIT();
            }
            mma_chunk(sb + (uint32_t)((t & 1) ? AH_OFF : 0), aoff, boff, acc);
        }
    }

    // convert Q(dc=0) into stage0 (dead after chunk 22; pending mma reads only AH)
    convertQ_g(Qf, 0, smem, tid);

    // ---- phase 2: mask bias + softmax in registers ----
    {
#pragma unroll
        for (int mi = 0; mi < 4; ++mi)
#pragma unroll
            for (int ni = 0; ni < 4; ++ni) {
                int q0 = wn * 32 + ni * 8 + cGrp;
                float b0 = qb[q0], b1 = qb[q0 + 1];
                acc[mi][ni][0] += b0; acc[mi][ni][1] += b1;
                acc[mi][ni][2] += b0; acc[mi][ni][3] += b1;
            }

        float mrow[4][2];
#pragma unroll
        for (int mi = 0; mi < 4; ++mi) {
            mrow[mi][0] = -INFINITY; mrow[mi][1] = -INFINITY;
#pragma unroll
            for (int ni = 0; ni < 4; ++ni) {
                mrow[mi][0] = fmaxf(mrow[mi][0], fmaxf(acc[mi][ni][0], acc[mi][ni][1]));
                mrow[mi][1] = fmaxf(mrow[mi][1], fmaxf(acc[mi][ni][2], acc[mi][ni][3]));
            }
        }
#pragma unroll
        for (int o = 1; o <= 2; o <<= 1)
#pragma unroll
            for (int mi = 0; mi < 4; ++mi) {
                mrow[mi][0] = fmaxf(mrow[mi][0], __shfl_xor_sync(0xFFFFFFFFu, mrow[mi][0], o));
                mrow[mi][1] = fmaxf(mrow[mi][1], __shfl_xor_sync(0xFFFFFFFFu, mrow[mi][1], o));
            }
        if ((lane & 3) == 0)
#pragma unroll
            for (int mi = 0; mi < 4; ++mi) {
                red[(wm * 64 + mi * 16 + rGrp) * 4 + wn]     = mrow[mi][0];
                red[(wm * 64 + mi * 16 + rGrp + 8) * 4 + wn] = mrow[mi][1];
            }
        __syncthreads();
        float M[4][2];
#pragma unroll
        for (int mi = 0; mi < 4; ++mi)
#pragma unroll
            for (int h = 0; h < 2; ++h) {
                const float* rr = &red[(wm * 64 + mi * 16 + rGrp + h * 8) * 4];
                M[mi][h] = fmaxf(fmaxf(rr[0], rr[1]), fmaxf(rr[2], rr[3]));
            }
        __syncthreads();

        float srow[4][2];
#pragma unroll
        for (int mi = 0; mi < 4; ++mi) { srow[mi][0] = 0.0f; srow[mi][1] = 0.0f; }
#pragma unroll
        for (int mi = 0; mi < 4; ++mi)
#pragma unroll
            for (int ni = 0; ni < 4; ++ni) {
                float e0 = __expf(acc[mi][ni][0] - M[mi][0]);
                float e1 = __expf(acc[mi][ni][1] - M[mi][0]);
                float e2 = __expf(acc[mi][ni][2] - M[mi][1]);
                float e3 = __expf(acc[mi][ni][3] - M[mi][1]);
                acc[mi][ni][0] = e0; acc[mi][ni][1] = e1;
                acc[mi][ni][2] = e2; acc[mi][ni][3] = e3;
                srow[mi][0] += e0 + e1;
                srow[mi][1] += e2 + e3;
            }
#pragma unroll
        for (int o = 1; o <= 2; o <<= 1)
#pragma unroll
            for (int mi = 0; mi < 4; ++mi) {
                srow[mi][0] += __shfl_xor_sync(0xFFFFFFFFu, srow[mi][0], o);
                srow[mi][1] += __shfl_xor_sync(0xFFFFFFFFu, srow[mi][1], o);
            }
        if ((lane & 3) == 0)
#pragma unroll
            for (int mi = 0; mi < 4; ++mi) {
                red[(wm * 64 + mi * 16 + rGrp) * 4 + wn]     = srow[mi][0];
                red[(wm * 64 + mi * 16 + rGrp + 8) * 4 + wn] = srow[mi][1];
            }
        __syncthreads();
        float INV[4][2];
#pragma unroll
        for (int mi = 0; mi < 4; ++mi)
#pragma unroll
            for (int h = 0; h < 2; ++h) {
                const float* rr = &red[(wm * 64 + mi * 16 + rGrp + h * 8) * 4];
                INV[mi][h] = 1.0f / (rr[0] + rr[1] + rr[2] + rr[3]);
            }

#pragma unroll
        for (int mi = 0; mi < 4; ++mi) {
            int pr = wm * 64 + mi * 16 + rGrp;
#pragma unroll
            for (int ni = 0; ni < 4; ++ni) {
                int q0 = wn * 32 + ni * 8 + cGrp;
                float a0 = acc[mi][ni][0] * INV[mi][0];
                float a1 = acc[mi][ni][1] * INV[mi][0];
                float a2 = acc[mi][ni][2] * INV[mi][1];
                float a3 = acc[mi][ni][3] * INV[mi][1];
                __nv_bfloat16 h0, h1, h2, h3, l0, l1, l2, l3;
                split2(a0, h0, l0); split2(a1, h1, l1);
                split2(a2, h2, l2); split2(a3, h3, l3);
                *(__nv_bfloat162*)(smem + AH_OFF + pr * AP_B + q0 * 2)       = __nv_bfloat162(h0, h1);
                *(__nv_bfloat162*)(smem + AL_OFF + pr * AP_B + q0 * 2)       = __nv_bfloat162(l0, l1);
                *(__nv_bfloat162*)(smem + AH_OFF + (pr + 8) * AP_B + q0 * 2) = __nv_bfloat162(h2, h3);
                *(__nv_bfloat162*)(smem + AL_OFF + (pr + 8) * AP_B + q0 * 2) = __nv_bfloat162(l2, l3);
            }
        }
    }
    __syncthreads();

    // ---- phase 3: out = alpha @ question; Q converted fp32->hi/lo per dc ----
    {
        uint32_t aoff3[4];
#pragma unroll
        for (int mi = 0; mi < 4; ++mi)
            aoff3[mi] = (uint32_t)(AH_OFF + (wm * 64 + mi * 16 + (j & 1) * 8 + rj) * AP_B + (j >> 1) * 16);
        uint32_t boffq = (uint32_t)(((j & 1) * 8 + rj) * QP_B + wn * 32 + (j >> 1) * 16);
        const uint32_t dAL = AL_OFF - AH_OFF;

        for (int dc = 0; dc < 12; ++dc) {
            if (dc > 0) {
                __syncthreads();   // WAR: all ldsm of Q(dc-1) complete
                convertQ_g(Qf, dc * 64, smem, tid);
                __syncthreads();   // STS visible
            }

            float o3[4][2][4];
#pragma unroll
            for (int mi = 0; mi < 4; ++mi)
#pragma unroll
                for (int ni = 0; ni < 2; ++ni)
#pragma unroll
                    for (int r = 0; r < 4; ++r) o3[mi][ni][r] = 0.0f;

#pragma unroll
            for (int ks = 0; ks < 8; ++ks) {
                uint32_t ka = (uint32_t)ks * 32;
                uint32_t kq = (uint32_t)ks * 16 * QP_B;
                uint32_t ah[4][4], bh[2][2];
#pragma unroll
                for (int mi = 0; mi < 4; ++mi)
                    ldsm4(ah[mi][0], ah[mi][1], ah[mi][2], ah[mi][3],
                          sb + aoff3[mi] + ka);
                {
                    uint32_t r0, r1, r2, r3;
                    ldsm4t(r0, r1, r2, r3, sb + boffq + kq);
                    bh[0][0] = r0; bh[0][1] = r1; bh[1][0] = r2; bh[1][1] = r3;
                }
#pragma unroll
                for (int mi = 0; mi < 4; ++mi)
#pragma unroll
                    for (int ni = 0; ni < 2; ++ni)
                        mma16816(o3[mi][ni], ah[mi][0], ah[mi][1], ah[mi][2], ah[mi][3],
                                 bh[ni][0], bh[ni][1]);
                uint32_t al[4][4];
#pragma unroll
                for (int mi = 0; mi < 4; ++mi)
                    ldsm4(al[mi][0], al[mi][1], al[mi][2], al[mi][3],
                          sb + aoff3[mi] + dAL + ka);
#pragma unroll
                for (int mi = 0; mi < 4; ++mi)
#pragma unroll
                    for (int ni = 0; ni < 2; ++ni)
                        mma16816(o3[mi][ni], al[mi][0], al[mi][1], al[mi][2], al[mi][3],
                                 bh[ni][0], bh[ni][1]);
                uint32_t bl[2][2];
                {
                    uint32_t r0, r1, r2, r3;
                    ldsm4t(r0, r1, r2, r3, sb + 18432 + boffq + kq);
                    bl[0][0] = r0; bl[0][1] = r1; bl[1][0] = r2; bl[1][1] = r3;
                }
#pragma unroll
                for (int mi = 0; mi < 4; ++mi)
#pragma unroll
                    for (int ni = 0; ni < 2; ++ni)
                        mma16816(o3[mi][ni], ah[mi][0], ah[mi][1], ah[mi][2], ah[mi][3],
                                 bl[ni][0], bl[ni][1]);
            }

#pragma unroll
            for (int mi = 0; mi < 4; ++mi) {
                size_t gr = (size_t)b * NLP + pBase + wm * 64 + mi * 16 + rGrp;
#pragma unroll
                for (int ni = 0; ni < 2; ++ni) {
                    int d = dc * 64 + wn * 16 + ni * 8 + cGrp;
                    float2 v0 = {o3[mi][ni][0], o3[mi][ni][1]};
                    float2 v1 = {o3[mi][ni][2], o3[mi][ni][3]};
                    *(float2*)(out + gr * DHID + d)       = v0;
                    *(float2*)(out + (gr + 8) * DHID + d) = v1;
                }
            }
        }
    }
}

// ---------------------------------------------------------------------------
extern "C" void kernel_launch(void* const* d_in, const int* in_sizes, int n_in,
                              void* d_out, int out_size) {
    const float* passage  = (const float*)d_in[0];
    const float* question = (const float*)d_in[2];
    const unsigned char* qmask = (const unsigned char*)d_in[3];
    const float* Ww = (const float*)d_in[4];
    const float* Wb = (const float*)d_in[5];
    float* out = (float*)d_out;

    __nv_bfloat16 *wth, *wtl, *wph, *wpl, *wqh, *wql;
    cudaGetSymbolAddress((void**)&wth, g_Wth);
    cudaGetSymbolAddress((void**)&wtl, g_Wtl);
    cudaGetSymbolAddress((void**)&wph, g_Wph);
    cudaGetSymbolAddress((void**)&wpl, g_Wpl);
    cudaGetSymbolAddress((void**)&wqh, g_Wqh);
    cudaGetSymbolAddress((void**)&wql, g_Wql);

    mask_prep_kernel<<<1, 256>>>(qmask, NB * NLQ);
    wsplit_kernel<<<dim3(DHID / 32, DHID / 32), dim3(32, 8)>>>(Ww, wth, wtl);

    cudaFuncSetAttribute(gemm_mma_kernel, cudaFuncAttributeMaxDynamicSharedMemorySize, GSMEM);
    gemm_mma_kernel<<<dim3(DHID / 128, YP + (NB * NLQ) / 128), 256, GSMEM>>>(
        passage, question, wth, wtl, Wb, wph, wpl, wqh, wql);

    cudaFuncSetAttribute(attn_tc_kernel, cudaFuncAttributeMaxDynamicSharedMemorySize, ASMEM);
    attn_tc_kernel<<<dim3(NLP / 128, NB), 256, ASMEM>>>(wph, wpl, wqh, wql, question, out);
}